// round 11
// baseline (speedup 1.0000x reference)
#include <cuda_runtime.h>

// Problem constants (from reference)
#define S_TOK   131072
#define DIM     512
#define VOCAB   100000
#define K_SLOTS 16        // ranks 0..15 per row; P(count>16) ~ 0 for lambda=0.655

// Scratch (device globals — zero at module load; the update kernel restores the
// all-zero invariant every run, so graph replays are self-consistent).
__device__ int g_counts[VOCAB];          // tokens per vocab row
__device__ int g_slot[VOCAB * K_SLOTS];  // token index per (row, rank). Never needs
                                         // clearing: only ranks < count are read.
__device__ int g_ovf_vidp1[S_TOK];       // overflow sentinel: vid+1 at token pos (0=empty)

// ---------------------------------------------------------------------------
// Kernel 1 (PDL primary): histogram + slot placement. 4 tokens per thread via
// int4 loads (4 independent atomic chains per thread).
// ---------------------------------------------------------------------------
__global__ void compact_kernel(const int4* __restrict__ l2_data4,
                               const int4* __restrict__ l2_idxs4) {
    int i = blockIdx.x * blockDim.x + threadIdx.x;   // i < S_TOK/4
    int4 idx = l2_idxs4[i];
    int4 dat = l2_data4[i];
    int base = i * 4;

    if (idx.x == 1) {
        int r = atomicAdd(&g_counts[dat.x], 1);
        if (r < K_SLOTS) g_slot[dat.x * K_SLOTS + r] = base;
        else             g_ovf_vidp1[base] = dat.x + 1;
    }
    if (idx.y == 1) {
        int r = atomicAdd(&g_counts[dat.y], 1);
        if (r < K_SLOTS) g_slot[dat.y * K_SLOTS + r] = base + 1;
        else             g_ovf_vidp1[base + 1] = dat.y + 1;
    }
    if (idx.z == 1) {
        int r = atomicAdd(&g_counts[dat.z], 1);
        if (r < K_SLOTS) g_slot[dat.z * K_SLOTS + r] = base + 2;
        else             g_ovf_vidp1[base + 2] = dat.z + 1;
    }
    if (idx.w == 1) {
        int r = atomicAdd(&g_counts[dat.w], 1);
        if (r < K_SLOTS) g_slot[dat.w * K_SLOTS + r] = base + 3;
        else             g_ovf_vidp1[base + 3] = dat.w + 1;
    }
}

// ---------------------------------------------------------------------------
// Kernel 2 (PDL secondary): update. Warp-per-row over ALL rows.
// Pre-wait: register-free L2 prefetch of this warp's w row (independent of
// compact's output — every path reads w). Then griddepcontrol.wait releases
// once compact has completed + flushed, and the R10-proven body runs.
// ---------------------------------------------------------------------------
__global__ void __launch_bounds__(256, 6)
update_kernel(const float4* __restrict__ x4,
              const float4* __restrict__ w4,
              float4* __restrict__ out4) {
    int row  = (blockIdx.x * blockDim.x + threadIdx.x) >> 5;
    int lane = threadIdx.x & 31;
    long base = (long)row * (DIM / 4);

    // Overlap window: stage this warp's w row (2KB = 16 x 128B lines) into L2
    // while the compact kernel is still running. No registers held.
    if (lane < 16) {
        const char* wp = (const char*)(w4 + base) + lane * 128;
        asm volatile("prefetch.global.L2 [%0];" :: "l"(wp));
    }

    // Block until compact's writes (counts/slots) are visible.
    asm volatile("griddepcontrol.wait;" ::: "memory");

    int c = g_counts[row];                 // uniform across warp

    if (c == 0) {
        float4 a = __ldcs(&w4[base + lane]);
        float4 b = __ldcs(&w4[base + lane + 32]);
        float4 d = __ldcs(&w4[base + lane + 64]);
        float4 e = __ldcs(&w4[base + lane + 96]);
        __stcs(&out4[base + lane],      a);
        __stcs(&out4[base + lane + 32], b);
        __stcs(&out4[base + lane + 64], d);
        __stcs(&out4[base + lane + 96], e);
        return;
    }

    if (lane == 0) g_counts[row] = 0;      // reset for next replay

    // --- gather ranks 0..min(c,K)-1 ---
    float4 s0 = make_float4(0.f, 0.f, 0.f, 0.f);
    float4 s1 = s0, s2 = s0, s3 = s0;

    int ns = (c < K_SLOTS) ? c : K_SLOTS;
    for (int t = 0; t < ns; t++) {
        int tok = g_slot[row * K_SLOTS + t];          // warp-uniform broadcast
        const float4* src = x4 + (long)tok * (DIM / 4);
        float4 a = __ldcs(&src[lane]);
        float4 b = __ldcs(&src[lane + 32]);
        float4 d = __ldcs(&src[lane + 64]);
        float4 e = __ldcs(&src[lane + 96]);
        s0.x += a.x; s0.y += a.y; s0.z += a.z; s0.w += a.w;
        s1.x += b.x; s1.y += b.y; s1.z += b.z; s1.w += b.w;
        s2.x += d.x; s2.y += d.y; s2.z += d.z; s2.w += d.w;
        s3.x += e.x; s3.y += e.y; s3.z += e.z; s3.w += e.w;
    }

    if (c > K_SLOTS) {
        // cold overflow path: correct for any input, never taken for this data
        int remaining = c - K_SLOTS;
        for (int b0 = 0; b0 < S_TOK && remaining > 0; b0 += 32) {
            int vpo = g_ovf_vidp1[b0 + lane];
            unsigned m = __ballot_sync(0xFFFFFFFFu, vpo == row + 1);
            while (m) {
                int j2 = b0 + (__ffs(m) - 1);
                m &= m - 1;
                const float4* src = x4 + (long)j2 * (DIM / 4);
                float4 a = src[lane];
                float4 b = src[lane + 32];
                float4 d = src[lane + 64];
                float4 e = src[lane + 96];
                s0.x += a.x; s0.y += a.y; s0.z += a.z; s0.w += a.w;
                s1.x += b.x; s1.y += b.y; s1.z += b.z; s1.w += b.w;
                s2.x += d.x; s2.y += d.y; s2.z += d.z; s2.w += d.w;
                s3.x += e.x; s3.y += e.y; s3.z += e.z; s3.w += e.w;
                if (lane == 0) g_ovf_vidp1[j2] = 0;   // consume + clear
                remaining--;
            }
        }
    }

    // --- final EMA write ---
    float inv = 0.5f / (float)c;
    float4 w0 = __ldcs(&w4[base + lane]);
    float4 w1 = __ldcs(&w4[base + lane + 32]);
    float4 w2 = __ldcs(&w4[base + lane + 64]);
    float4 w3 = __ldcs(&w4[base + lane + 96]);
    __stcs(&out4[base + lane], make_float4(
        fmaf(s0.x, inv, 0.5f * w0.x), fmaf(s0.y, inv, 0.5f * w0.y),
        fmaf(s0.z, inv, 0.5f * w0.z), fmaf(s0.w, inv, 0.5f * w0.w)));
    __stcs(&out4[base + lane + 32], make_float4(
        fmaf(s1.x, inv, 0.5f * w1.x), fmaf(s1.y, inv, 0.5f * w1.y),
        fmaf(s1.z, inv, 0.5f * w1.z), fmaf(s1.w, inv, 0.5f * w1.w)));
    __stcs(&out4[base + lane + 64], make_float4(
        fmaf(s2.x, inv, 0.5f * w2.x), fmaf(s2.y, inv, 0.5f * w2.y),
        fmaf(s2.z, inv, 0.5f * w2.z), fmaf(s2.w, inv, 0.5f * w2.w)));
    __stcs(&out4[base + lane + 96], make_float4(
        fmaf(s3.x, inv, 0.5f * w3.x), fmaf(s3.y, inv, 0.5f * w3.y),
        fmaf(s3.z, inv, 0.5f * w3.z), fmaf(s3.w, inv, 0.5f * w3.w)));
}

// ---------------------------------------------------------------------------
extern "C" void kernel_launch(void* const* d_in, const int* in_sizes, int n_in,
                              void* d_out, int out_size) {
    const float* out_act   = (const float*)d_in[0];   // [S, D] f32
    const float* l2_weight = (const float*)d_in[1];   // [V, D] f32
    const int*   l2_data   = (const int*)d_in[2];     // [S] i32
    const int*   l2_idxs   = (const int*)d_in[3];     // [S] i32
    float* outp = (float*)d_out;                      // [V, D] f32

    (void)in_sizes; (void)n_in; (void)out_size;

    // 1. compact (PDL primary; scratch all-zero on entry)
    compact_kernel<<<S_TOK / 4 / 256, 256>>>((const int4*)l2_data,
                                             (const int4*)l2_idxs);

    // 2. update as PDL secondary: may begin scheduling while compact runs;
    //    its pre-wait prefetches overlap compact, griddepcontrol.wait gates
    //    the dependent reads.
    {
        cudaLaunchConfig_t cfg = {};
        cfg.gridDim  = dim3(VOCAB / 8);
        cfg.blockDim = dim3(256);
        cfg.dynamicSmemBytes = 0;
        cfg.stream = 0;   // legacy default stream (same one the harness captures)

        cudaLaunchAttribute attr[1];
        attr[0].id = cudaLaunchAttributeProgrammaticStreamSerialization;
        attr[0].val.programmaticStreamSerializationAllowed = 1;
        cfg.attrs = attr;
        cfg.numAttrs = 1;

        cudaLaunchKernelEx(&cfg, update_kernel,
                           (const float4*)out_act,
                           (const float4*)l2_weight,
                           (float4*)outp);
    }
}

// round 12
// speedup vs baseline: 1.0003x; 1.0003x over previous
#include <cuda_runtime.h>

// Problem constants (from reference)
#define S_TOK   131072
#define DIM     512
#define VOCAB   100000
#define K_SLOTS 16        // ranks 0..15 per row; P(count>16) ~ 0 for lambda=0.655

// Scratch (device globals — zero at module load; the update kernel restores the
// all-zero invariant every run, so graph replays are self-consistent).
__device__ int g_counts[VOCAB];          // tokens per vocab row
__device__ int g_slot[VOCAB * K_SLOTS];  // token index per (row, rank). Never needs
                                         // clearing: only ranks < count are read.
__device__ int g_ovf_vidp1[S_TOK];       // overflow sentinel: vid+1 at token pos (0=empty)

// ---------------------------------------------------------------------------
// Kernel 1: histogram + slot placement. 4 tokens per thread via int4 loads
// (4 independent atomic chains per thread, MLP=4).
// ---------------------------------------------------------------------------
__global__ void compact_kernel(const int4* __restrict__ l2_data4,
                               const int4* __restrict__ l2_idxs4) {
    int i = blockIdx.x * blockDim.x + threadIdx.x;   // i < S_TOK/4
    int4 idx = l2_idxs4[i];
    int4 dat = l2_data4[i];
    int base = i * 4;

    if (idx.x == 1) {
        int r = atomicAdd(&g_counts[dat.x], 1);
        if (r < K_SLOTS) g_slot[dat.x * K_SLOTS + r] = base;
        else             g_ovf_vidp1[base] = dat.x + 1;
    }
    if (idx.y == 1) {
        int r = atomicAdd(&g_counts[dat.y], 1);
        if (r < K_SLOTS) g_slot[dat.y * K_SLOTS + r] = base + 1;
        else             g_ovf_vidp1[base + 1] = dat.y + 1;
    }
    if (idx.z == 1) {
        int r = atomicAdd(&g_counts[dat.z], 1);
        if (r < K_SLOTS) g_slot[dat.z * K_SLOTS + r] = base + 2;
        else             g_ovf_vidp1[base + 2] = dat.z + 1;
    }
    if (idx.w == 1) {
        int r = atomicAdd(&g_counts[dat.w], 1);
        if (r < K_SLOTS) g_slot[dat.w * K_SLOTS + r] = base + 3;
        else             g_ovf_vidp1[base + 3] = dat.w + 1;
    }
}

// ---------------------------------------------------------------------------
// Kernel 2: update. Warp-per-row over ALL rows (exact grid: VOCAB/8 blocks).
// Entry: register-free L2 prefetch of this warp's w row — issues 16
// independent line fills ahead of the dependent count->branch->w chain
// (measured -1.7us on this kernel in R11).
//   c==0 -> out = w (streaming copy; 52% of rows — saturates DRAM and hides
//           the gather warps' dependent-load latency)
//   c>=1 -> gather the c token rows from slots, single EMA write
// No atomics, no seed writes: every output byte written exactly once.
// Scratch reset folded in race-free (each warp owns its row's count).
// ---------------------------------------------------------------------------
__global__ void __launch_bounds__(256, 6)
update_kernel(const float4* __restrict__ x4,
              const float4* __restrict__ w4,
              float4* __restrict__ out4) {
    int row  = (blockIdx.x * blockDim.x + threadIdx.x) >> 5;
    int lane = threadIdx.x & 31;
    long base = (long)row * (DIM / 4);

    // Early MLP: stage this warp's w row (2KB = 16 x 128B lines) into L2
    // before the dependent count load resolves. No registers held.
    if (lane < 16) {
        const char* wp = (const char*)(w4 + base) + lane * 128;
        asm volatile("prefetch.global.L2 [%0];" :: "l"(wp));
    }

    int c = g_counts[row];                 // uniform across warp

    if (c == 0) {
        float4 a = __ldcs(&w4[base + lane]);
        float4 b = __ldcs(&w4[base + lane + 32]);
        float4 d = __ldcs(&w4[base + lane + 64]);
        float4 e = __ldcs(&w4[base + lane + 96]);
        __stcs(&out4[base + lane],      a);
        __stcs(&out4[base + lane + 32], b);
        __stcs(&out4[base + lane + 64], d);
        __stcs(&out4[base + lane + 96], e);
        return;
    }

    if (lane == 0) g_counts[row] = 0;      // reset for next replay

    // --- gather ranks 0..min(c,K)-1 ---
    float4 s0 = make_float4(0.f, 0.f, 0.f, 0.f);
    float4 s1 = s0, s2 = s0, s3 = s0;

    int ns = (c < K_SLOTS) ? c : K_SLOTS;
    for (int t = 0; t < ns; t++) {
        int tok = g_slot[row * K_SLOTS + t];          // warp-uniform broadcast
        const float4* src = x4 + (long)tok * (DIM / 4);
        float4 a = __ldcs(&src[lane]);
        float4 b = __ldcs(&src[lane + 32]);
        float4 d = __ldcs(&src[lane + 64]);
        float4 e = __ldcs(&src[lane + 96]);
        s0.x += a.x; s0.y += a.y; s0.z += a.z; s0.w += a.w;
        s1.x += b.x; s1.y += b.y; s1.z += b.z; s1.w += b.w;
        s2.x += d.x; s2.y += d.y; s2.z += d.z; s2.w += d.w;
        s3.x += e.x; s3.y += e.y; s3.z += e.z; s3.w += e.w;
    }

    if (c > K_SLOTS) {
        // cold overflow path: correct for any input, never taken for this data
        int remaining = c - K_SLOTS;
        for (int b0 = 0; b0 < S_TOK && remaining > 0; b0 += 32) {
            int vpo = g_ovf_vidp1[b0 + lane];
            unsigned m = __ballot_sync(0xFFFFFFFFu, vpo == row + 1);
            while (m) {
                int j2 = b0 + (__ffs(m) - 1);
                m &= m - 1;
                const float4* src = x4 + (long)j2 * (DIM / 4);
                float4 a = src[lane];
                float4 b = src[lane + 32];
                float4 d = src[lane + 64];
                float4 e = src[lane + 96];
                s0.x += a.x; s0.y += a.y; s0.z += a.z; s0.w += a.w;
                s1.x += b.x; s1.y += b.y; s1.z += b.z; s1.w += b.w;
                s2.x += d.x; s2.y += d.y; s2.z += d.z; s2.w += d.w;
                s3.x += e.x; s3.y += e.y; s3.z += e.z; s3.w += e.w;
                if (lane == 0) g_ovf_vidp1[j2] = 0;   // consume + clear
                remaining--;
            }
        }
    }

    // --- final EMA write ---
    float inv = 0.5f / (float)c;
    float4 w0 = __ldcs(&w4[base + lane]);
    float4 w1 = __ldcs(&w4[base + lane + 32]);
    float4 w2 = __ldcs(&w4[base + lane + 64]);
    float4 w3 = __ldcs(&w4[base + lane + 96]);
    __stcs(&out4[base + lane], make_float4(
        fmaf(s0.x, inv, 0.5f * w0.x), fmaf(s0.y, inv, 0.5f * w0.y),
        fmaf(s0.z, inv, 0.5f * w0.z), fmaf(s0.w, inv, 0.5f * w0.w)));
    __stcs(&out4[base + lane + 32], make_float4(
        fmaf(s1.x, inv, 0.5f * w1.x), fmaf(s1.y, inv, 0.5f * w1.y),
        fmaf(s1.z, inv, 0.5f * w1.z), fmaf(s1.w, inv, 0.5f * w1.w)));
    __stcs(&out4[base + lane + 64], make_float4(
        fmaf(s2.x, inv, 0.5f * w2.x), fmaf(s2.y, inv, 0.5f * w2.y),
        fmaf(s2.z, inv, 0.5f * w2.z), fmaf(s2.w, inv, 0.5f * w2.w)));
    __stcs(&out4[base + lane + 96], make_float4(
        fmaf(s3.x, inv, 0.5f * w3.x), fmaf(s3.y, inv, 0.5f * w3.y),
        fmaf(s3.z, inv, 0.5f * w3.z), fmaf(s3.w, inv, 0.5f * w3.w)));
}

// ---------------------------------------------------------------------------
extern "C" void kernel_launch(void* const* d_in, const int* in_sizes, int n_in,
                              void* d_out, int out_size) {
    const float* out_act   = (const float*)d_in[0];   // [S, D] f32
    const float* l2_weight = (const float*)d_in[1];   // [V, D] f32
    const int*   l2_data   = (const int*)d_in[2];     // [S] i32
    const int*   l2_idxs   = (const int*)d_in[3];     // [S] i32
    float* outp = (float*)d_out;                      // [V, D] f32

    (void)in_sizes; (void)n_in; (void)out_size;

    // 1. histogram + slots (scratch all-zero on entry; 4 tokens/thread)
    compact_kernel<<<S_TOK / 4 / 256, 256>>>((const int4*)l2_data,
                                             (const int4*)l2_idxs);

    // 2. update: c==0 copy + c>=1 gather-EMA + scratch reset (warp-per-row)
    update_kernel<<<VOCAB / 8, 256>>>((const float4*)out_act,
                                      (const float4*)l2_weight,
                                      (float4*)outp);
}

// round 13
// speedup vs baseline: 1.0304x; 1.0300x over previous
#include <cuda_runtime.h>

// Problem constants (from reference)
#define S_TOK   131072
#define DIM     512
#define VOCAB   100000
#define K_SLOTS 16        // ranks 0..15 per row; P(count>16) ~ 0 for lambda=0.655

// Scratch (device globals — zero at module load; the update kernel restores the
// all-zero invariant every run, so graph replays are self-consistent).
__device__ int g_counts[VOCAB];          // tokens per vocab row
__device__ int g_slot[VOCAB * K_SLOTS];  // token index per (row, rank). Never needs
                                         // clearing: only ranks < count are read.
__device__ int g_ovf_vidp1[S_TOK];       // overflow sentinel: vid+1 at token pos (0=empty)

// ---------------------------------------------------------------------------
// Kernel 1: histogram + slot placement. 4 tokens per thread via int4 loads
// (4 independent atomic chains per thread, MLP=4). 128-thread blocks so the
// grid is 256 blocks — ~2 per SM across 148 SMs (R10's 128 blocks left SMs
// idle and concentrated the atomic traffic).
// ---------------------------------------------------------------------------
__global__ void compact_kernel(const int4* __restrict__ l2_data4,
                               const int4* __restrict__ l2_idxs4) {
    int i = blockIdx.x * blockDim.x + threadIdx.x;   // i < S_TOK/4
    int4 idx = l2_idxs4[i];
    int4 dat = l2_data4[i];
    int base = i * 4;

    if (idx.x == 1) {
        int r = atomicAdd(&g_counts[dat.x], 1);
        if (r < K_SLOTS) g_slot[dat.x * K_SLOTS + r] = base;
        else             g_ovf_vidp1[base] = dat.x + 1;
    }
    if (idx.y == 1) {
        int r = atomicAdd(&g_counts[dat.y], 1);
        if (r < K_SLOTS) g_slot[dat.y * K_SLOTS + r] = base + 1;
        else             g_ovf_vidp1[base + 1] = dat.y + 1;
    }
    if (idx.z == 1) {
        int r = atomicAdd(&g_counts[dat.z], 1);
        if (r < K_SLOTS) g_slot[dat.z * K_SLOTS + r] = base + 2;
        else             g_ovf_vidp1[base + 2] = dat.z + 1;
    }
    if (idx.w == 1) {
        int r = atomicAdd(&g_counts[dat.w], 1);
        if (r < K_SLOTS) g_slot[dat.w * K_SLOTS + r] = base + 3;
        else             g_ovf_vidp1[base + 3] = dat.w + 1;
    }
}

// ---------------------------------------------------------------------------
// Kernel 2: update (exact R10 body — best measured total). Warp-per-row over
// ALL rows (exact grid: VOCAB/8 blocks of 256).
//   c==0 -> out = w (streaming copy; 52% of rows — saturates DRAM and hides
//           the gather warps' dependent-load latency)
//   c>=1 -> gather the c token rows from slots, single EMA write
// No atomics, no seed writes: every output byte written exactly once.
// Scratch reset folded in race-free (each warp owns its row's count).
// NOTE: no L2 prefetch — it looked good under isolated ncu (-1.7us kernel) but
// cost +2us total in graph-replay steady state across two rounds.
// ---------------------------------------------------------------------------
__global__ void __launch_bounds__(256, 6)
update_kernel(const float4* __restrict__ x4,
              const float4* __restrict__ w4,
              float4* __restrict__ out4) {
    int row  = (blockIdx.x * blockDim.x + threadIdx.x) >> 5;
    int lane = threadIdx.x & 31;

    int c = g_counts[row];                 // uniform across warp
    long base = (long)row * (DIM / 4);

    if (c == 0) {
        float4 a = __ldcs(&w4[base + lane]);
        float4 b = __ldcs(&w4[base + lane + 32]);
        float4 d = __ldcs(&w4[base + lane + 64]);
        float4 e = __ldcs(&w4[base + lane + 96]);
        __stcs(&out4[base + lane],      a);
        __stcs(&out4[base + lane + 32], b);
        __stcs(&out4[base + lane + 64], d);
        __stcs(&out4[base + lane + 96], e);
        return;
    }

    if (lane == 0) g_counts[row] = 0;      // reset for next replay

    // --- gather ranks 0..min(c,K)-1 ---
    float4 s0 = make_float4(0.f, 0.f, 0.f, 0.f);
    float4 s1 = s0, s2 = s0, s3 = s0;

    int ns = (c < K_SLOTS) ? c : K_SLOTS;
    for (int t = 0; t < ns; t++) {
        int tok = g_slot[row * K_SLOTS + t];          // warp-uniform broadcast
        const float4* src = x4 + (long)tok * (DIM / 4);
        float4 a = __ldcs(&src[lane]);
        float4 b = __ldcs(&src[lane + 32]);
        float4 d = __ldcs(&src[lane + 64]);
        float4 e = __ldcs(&src[lane + 96]);
        s0.x += a.x; s0.y += a.y; s0.z += a.z; s0.w += a.w;
        s1.x += b.x; s1.y += b.y; s1.z += b.z; s1.w += b.w;
        s2.x += d.x; s2.y += d.y; s2.z += d.z; s2.w += d.w;
        s3.x += e.x; s3.y += e.y; s3.z += e.z; s3.w += e.w;
    }

    if (c > K_SLOTS) {
        // cold overflow path: correct for any input, never taken for this data
        int remaining = c - K_SLOTS;
        for (int b0 = 0; b0 < S_TOK && remaining > 0; b0 += 32) {
            int vpo = g_ovf_vidp1[b0 + lane];
            unsigned m = __ballot_sync(0xFFFFFFFFu, vpo == row + 1);
            while (m) {
                int j2 = b0 + (__ffs(m) - 1);
                m &= m - 1;
                const float4* src = x4 + (long)j2 * (DIM / 4);
                float4 a = src[lane];
                float4 b = src[lane + 32];
                float4 d = src[lane + 64];
                float4 e = src[lane + 96];
                s0.x += a.x; s0.y += a.y; s0.z += a.z; s0.w += a.w;
                s1.x += b.x; s1.y += b.y; s1.z += b.z; s1.w += b.w;
                s2.x += d.x; s2.y += d.y; s2.z += d.z; s2.w += d.w;
                s3.x += e.x; s3.y += e.y; s3.z += e.z; s3.w += e.w;
                if (lane == 0) g_ovf_vidp1[j2] = 0;   // consume + clear
                remaining--;
            }
        }
    }

    // --- final EMA write ---
    float inv = 0.5f / (float)c;
    float4 w0 = __ldcs(&w4[base + lane]);
    float4 w1 = __ldcs(&w4[base + lane + 32]);
    float4 w2 = __ldcs(&w4[base + lane + 64]);
    float4 w3 = __ldcs(&w4[base + lane + 96]);
    __stcs(&out4[base + lane], make_float4(
        fmaf(s0.x, inv, 0.5f * w0.x), fmaf(s0.y, inv, 0.5f * w0.y),
        fmaf(s0.z, inv, 0.5f * w0.z), fmaf(s0.w, inv, 0.5f * w0.w)));
    __stcs(&out4[base + lane + 32], make_float4(
        fmaf(s1.x, inv, 0.5f * w1.x), fmaf(s1.y, inv, 0.5f * w1.y),
        fmaf(s1.z, inv, 0.5f * w1.z), fmaf(s1.w, inv, 0.5f * w1.w)));
    __stcs(&out4[base + lane + 64], make_float4(
        fmaf(s2.x, inv, 0.5f * w2.x), fmaf(s2.y, inv, 0.5f * w2.y),
        fmaf(s2.z, inv, 0.5f * w2.z), fmaf(s2.w, inv, 0.5f * w2.w)));
    __stcs(&out4[base + lane + 96], make_float4(
        fmaf(s3.x, inv, 0.5f * w3.x), fmaf(s3.y, inv, 0.5f * w3.y),
        fmaf(s3.z, inv, 0.5f * w3.z), fmaf(s3.w, inv, 0.5f * w3.w)));
}

// ---------------------------------------------------------------------------
extern "C" void kernel_launch(void* const* d_in, const int* in_sizes, int n_in,
                              void* d_out, int out_size) {
    const float* out_act   = (const float*)d_in[0];   // [S, D] f32
    const float* l2_weight = (const float*)d_in[1];   // [V, D] f32
    const int*   l2_data   = (const int*)d_in[2];     // [S] i32
    const int*   l2_idxs   = (const int*)d_in[3];     // [S] i32
    float* outp = (float*)d_out;                      // [V, D] f32

    (void)in_sizes; (void)n_in; (void)out_size;

    // 1. histogram + slots (scratch all-zero on entry; 4 tokens/thread,
    //    128-thread blocks -> 256 blocks across 148 SMs)
    compact_kernel<<<S_TOK / 4 / 128, 128>>>((const int4*)l2_data,
                                             (const int4*)l2_idxs);

    // 2. update: c==0 copy + c>=1 gather-EMA + scratch reset (warp-per-row)
    update_kernel<<<VOCAB / 8, 256>>>((const float4*)out_act,
                                      (const float4*)l2_weight,
                                      (float4*)outp);
}